// round 16
// baseline (speedup 1.0000x reference)
#include <cuda_runtime.h>
#include <math_constants.h>

#define NN      1024
#define HID     128
#define HEADS   4
#define HD      32
#define LAYERS  3
#define TI      4          // i-rows per block in attention
#define NSEG    4          // j-segments (warp = head x seg)
#define SEGJ    (NN/NSEG)  // 256
#define ADJW    (NN/32)    // 32 words per adjacency row
#define GRID    256
#define TPB     512

typedef unsigned long long u64;

#define FMA2(acc, x, y) asm("fma.rn.f32x2 %0, %1, %2, %0;" : "+l"(acc) : "l"(x), "l"(y))

__device__ __forceinline__ u64 absadd2(u64 x, u64 y) {
    u64 s;
    asm("add.rn.f32x2 %0, %1, %2;" : "=l"(s) : "l"(x), "l"(y));
    return s & 0x7FFFFFFF7FFFFFFFull;   // packed fabs (LOP3, ALU pipe)
}

__device__ __forceinline__ float unpack_sum(u64 v) {
    float lo, hi;
    asm("mov.b64 {%0, %1}, %2;" : "=f"(lo), "=f"(hi) : "l"(v));
    return lo + hi;
}

__device__ __forceinline__ u64 pack2(float lo, float hi) {
    u64 r;
    asm("mov.b64 %0, {%1, %2};" : "=l"(r) : "f"(lo), "f"(hi));
    return r;
}

__device__ __forceinline__ float ex2f(float x) {
    float r;
    asm("ex2.approx.f32 %0, %1;" : "=f"(r) : "f"(x));
    return r;
}

#define LOG2E 1.4426950408889634f

// ---------------- scratch (no allocs allowed) ----------------
__device__ __align__(128) float    g_h[NN * HID];
__device__ __align__(128) float    g_wlh[NN * HID];
__device__ __align__(128) float    g_wrhT[HID * NN];     // pair-interleaved: [h*16+dp][j][2]
__device__ __align__(128) float    g_v[NN * HID];        // pair-interleaved: [(j>>1)][d][j&1]
__device__ __align__(128) float    g_eb[HEADS * NN];     // log2-domain: 0.6*log2e*sum_d wrh*att
__device__ __align__(128) unsigned g_adjbits[ADJW * NN]; // [word][i] transposed
__device__ __align__(128) float    g_pool[GRID * HID];   // per-block column partials

// ---------------- grid barrier (generation-based, persistent-safe) ----------------
__device__ unsigned          g_cnt = 0;
__device__ volatile unsigned g_gen = 0;

__device__ __forceinline__ void grid_sync() {
    __syncthreads();
    if (threadIdx.x == 0) {
        __threadfence();                       // publish writes + L1 IVALL
        unsigned gen = g_gen;
        if (atomicAdd(&g_cnt, 1) == GRID - 1) {
            g_cnt = 0;
            __threadfence();
            g_gen = gen + 1;
        } else {
            while (g_gen == gen) __nanosleep(32);
        }
        __threadfence();                       // invalidate L1 before new reads
    }
    __syncthreads();
}

// ---------------- shared memory union ----------------
struct AttnSmem {
    float wl[TI][HID];
    float att[HD];
    float p[16][2][TI][32];             // [warp][parity][ii][jj] double-buffered
    float s[HEADS][NSEG][TI];
    float acc[HEADS][NSEG][TI][HD];
    float agg[TI][HID];                 // also final-h rows in last layer
};
struct GemmSmem { float hs[16 * 132]; };
union MegaSmem {
    AttnSmem  a;
    GemmSmem  g;
    float     ps[HID];
};

__global__ void __launch_bounds__(TPB, 2)
mega_kernel(const float* __restrict__ nf,   const float* __restrict__ adj,
            const float* __restrict__ Wp,   const float* __restrict__ bp,
            const float* __restrict__ Wl,   const float* __restrict__ Wr,
            const float* __restrict__ Wv,   const float* __restrict__ att,
            const float* __restrict__ gamma,const float* __restrict__ beta,
            const float* __restrict__ Wn1,  const float* __restrict__ bn1,
            const float* __restrict__ Wn2,  const float* __restrict__ bn2,
            const float* __restrict__ Wd1,  const float* __restrict__ bd1,
            const float* __restrict__ Wd2,  const float* __restrict__ bd2,
            const float* __restrict__ Wv1,  const float* __restrict__ bv1,
            const float* __restrict__ Wv2,  const float* __restrict__ bv2,
            float* __restrict__ out) {
    __shared__ MegaSmem sm;
    __shared__ float redA[4][4], redB[4][4];
    const int b    = blockIdx.x;
    const int tid  = threadIdx.x;
    const int warp = tid >> 5;
    const int lane = tid & 31;

    // ================= phase 0: proj + adjbits =================
    {
        int t = b * TPB + tid;            // 0..131071
        int i = t >> 7, c = t & 127;
        float a = bp[c]
                + nf[i * 3 + 0] * Wp[0 * HID + c]
                + nf[i * 3 + 1] * Wp[1 * HID + c]
                + nf[i * 3 + 2] * Wp[2 * HID + c];
        g_h[i * HID + c] = fmaxf(a, 0.f);

        int gw  = b * 16 + warp;          // 0..4095
        int row = gw >> 2, part = gw & 3;
#pragma unroll
        for (int q = 0; q < 8; q++) {
            int w2 = part * 8 + q;
            float v = adj[(size_t)row * NN + w2 * 32 + lane];
            unsigned bits = __ballot_sync(0xffffffffu, v > 0.5f);
            if (lane == 0) g_adjbits[w2 * NN + row] = bits;
        }
    }
    grid_sync();

    // ================= layers =================
    for (int l = 0; l < LAYERS; l++) {
        const float* attL = att + l * HD;

        // ---- gemm3 phase: blocks 0..191, 16 rows/block ----
        if (b < 192) {
            int mode = b >> 6;
            int r0   = (b & 63) * 16;
            const float* W = (mode == 0 ? Wl : (mode == 1 ? Wr : Wv)) + l * HID * HID;
            float* hs = sm.g.hs;
            for (int t = tid; t < 16 * HID; t += TPB)
                hs[(t >> 7) * 132 + (t & 127)] = g_h[r0 * HID + t];
            __syncthreads();

            int c = tid & 127, rg = tid >> 7;   // 4 row-groups x 4 rows
            float acc[4] = {0.f, 0.f, 0.f, 0.f};
#pragma unroll 4
            for (int k4 = 0; k4 < HID / 4; k4++) {
                float w0 = W[(4 * k4 + 0) * HID + c];
                float w1 = W[(4 * k4 + 1) * HID + c];
                float w2 = W[(4 * k4 + 2) * HID + c];
                float w3 = W[(4 * k4 + 3) * HID + c];
#pragma unroll
                for (int r = 0; r < 4; r++) {
                    float4 hv = *(const float4*)&hs[(rg * 4 + r) * 132 + 4 * k4];
                    acc[r] = fmaf(hv.x, w0, acc[r]);
                    acc[r] = fmaf(hv.y, w1, acc[r]);
                    acc[r] = fmaf(hv.z, w2, acc[r]);
                    acc[r] = fmaf(hv.w, w3, acc[r]);
                }
            }

            if (mode == 0) {
#pragma unroll
                for (int r = 0; r < 4; r++)
                    g_wlh[(r0 + rg * 4 + r) * HID + c] = acc[r];
            } else if (mode == 2) {
                // pair-interleaved V: [(row>>1)][d][row&1]
#pragma unroll
                for (int r = 0; r < 4; r++) {
                    int row = r0 + rg * 4 + r;
                    g_v[(row >> 1) * (2 * HID) + c * 2 + (row & 1)] = acc[r];
                }
            } else {
                // eb (log2 domain): warp covers (rg, head = warp&3), c = head*32 + lane
                int head = warp & 3;
                float atv = attL[lane];
#pragma unroll
                for (int r = 0; r < 4; r++) {
                    float bv = acc[r] * atv;
#pragma unroll
                    for (int o = 16; o; o >>= 1) bv += __shfl_xor_sync(0xffffffffu, bv, o);
                    if (lane == 0) g_eb[head * NN + r0 + rg * 4 + r] = 0.6f * LOG2E * bv;
                }
                __syncthreads();
#pragma unroll
                for (int r = 0; r < 4; r++)
                    hs[(rg * 4 + r) * 132 + c] = acc[r];
                __syncthreads();
                // pair-interleaved wrhT: [(cc>>1)][j][cc&1]
                int l16 = tid & 15, grp = tid >> 4;   // 32 groups x 16 lanes
                for (int cc = grp; cc < HID; cc += 32)
                    g_wrhT[((cc >> 1) * NN + r0 + l16) * 2 + (cc & 1)] = hs[l16 * 132 + cc];
            }
        }
        grid_sync();

        // ---- attn phase: all 256 blocks ----
        {
            const int i0  = b * TI;
            const int h   = warp & 3;
            const int seg = warp >> 2;

            for (int t = tid; t < TI * HID; t += TPB)
                sm.a.wl[t >> 7][t & 127] = g_wlh[i0 * HID + t];
            // fold 0.4 * log2(e): hot path uses raw ex2
            if (tid < HD) sm.a.att[tid] = 0.4f * LOG2E * attL[tid];
            __syncthreads();

            float s0 = 0.f, s1 = 0.f, s2 = 0.f, s3 = 0.f;
            u64 a20 = 0, a21 = 0, a22 = 0, a23 = 0;   // packed even/odd-jj agg partials

            const int jbase = seg * SEGJ;

            // scalar prefetch for chunk 0
            float leb = g_eb[h * NN + jbase + lane];
            uint4 aw  = *(const uint4*)&g_adjbits[(jbase >> 5) * NN + i0];

#pragma unroll 1
            for (int c = 0; c < SEGJ / 32; c++) {
                const int j0  = jbase + c * 32;
                const int j   = j0 + lane;
                const int par = c & 1;

                // init score accumulators with {leb, 0}: the bias rides the FMA2 chain
                u64 linit = pack2(leb, 0.f);
                u64 c20 = linit, c21 = linit, c22 = linit, c23 = linit;
#pragma unroll
                for (int half = 0; half < 2; half++) {
                    u64 wru[8];
#pragma unroll
                    for (int dp = 0; dp < 8; dp++)
                        wru[dp] = *(const u64*)&g_wrhT[((h * 16 + half * 8 + dp) * NN + j) * 2];
#pragma unroll
                    for (int q = 0; q < 4; q++) {
                        ulonglong2 at2 = *(const ulonglong2*)&sm.a.att[half * 16 + 4 * q];
                        u64 wa = wru[2 * q], wb = wru[2 * q + 1];
                        const int off = h * HD + half * 16 + 4 * q;
                        ulonglong2 lw;
                        lw = *(const ulonglong2*)&sm.a.wl[0][off];
                        FMA2(c20, absadd2(lw.x, wa), at2.x);
                        FMA2(c20, absadd2(lw.y, wb), at2.y);
                        lw = *(const ulonglong2*)&sm.a.wl[1][off];
                        FMA2(c21, absadd2(lw.x, wa), at2.x);
                        FMA2(c21, absadd2(lw.y, wb), at2.y);
                        lw = *(const ulonglong2*)&sm.a.wl[2][off];
                        FMA2(c22, absadd2(lw.x, wa), at2.x);
                        FMA2(c22, absadd2(lw.y, wb), at2.y);
                        lw = *(const ulonglong2*)&sm.a.wl[3][off];
                        FMA2(c23, absadd2(lw.x, wa), at2.x);
                        FMA2(c23, absadd2(lw.y, wb), at2.y);
                    }
                }

                float e0 = unpack_sum(c20);
                float e1 = unpack_sum(c21);
                float e2 = unpack_sum(c22);
                float e3 = unpack_sum(c23);
                float p0 = ((aw.x >> lane) & 1u) ? ex2f(e0) : 0.f;
                float p1 = ((aw.y >> lane) & 1u) ? ex2f(e1) : 0.f;
                float p2 = ((aw.z >> lane) & 1u) ? ex2f(e2) : 0.f;
                float p3 = ((aw.w >> lane) & 1u) ? ex2f(e3) : 0.f;
                s0 += p0; s1 += p1; s2 += p2; s3 += p3;

                // transposed store into parity buffer: p[warp][par][ii][jj=lane]
                sm.a.p[warp][par][0][lane] = p0;
                sm.a.p[warp][par][1][lane] = p1;
                sm.a.p[warp][par][2][lane] = p2;
                sm.a.p[warp][par][3][lane] = p3;
                __syncwarp();

                // scalar prefetch for chunk c+1 (5 regs, covered by the agg section)
                if (c + 1 < SEGJ / 32) {
                    leb = g_eb[h * NN + j0 + 32 + lane];
                    aw  = *(const uint4*)&g_adjbits[((j0 + 32) >> 5) * NN + i0];
                }

                // ---- packed aggregation: LDS.128 p-quads + FFMA2 ----
                const float* vp = g_v + (size_t)(j0 >> 1) * (2 * HID) + (h * HD + lane) * 2;
#pragma unroll
                for (int k = 0; k < 8; k++) {
                    u64 vva = *(const u64*)(vp + (2 * k)     * (2 * HID));
                    u64 vvb = *(const u64*)(vp + (2 * k + 1) * (2 * HID));
                    ulonglong2 q0 = *(const ulonglong2*)&sm.a.p[warp][par][0][4 * k];
                    ulonglong2 q1 = *(const ulonglong2*)&sm.a.p[warp][par][1][4 * k];
                    ulonglong2 q2 = *(const ulonglong2*)&sm.a.p[warp][par][2][4 * k];
                    ulonglong2 q3 = *(const ulonglong2*)&sm.a.p[warp][par][3][4 * k];
                    FMA2(a20, q0.x, vva);
                    FMA2(a21, q1.x, vva);
                    FMA2(a22, q2.x, vva);
                    FMA2(a23, q3.x, vva);
                    FMA2(a20, q0.y, vvb);
                    FMA2(a21, q1.y, vvb);
                    FMA2(a22, q2.y, vvb);
                    FMA2(a23, q3.y, vvb);
                }
                // no trailing syncwarp: next chunk writes the other parity buffer;
                // its post-store syncwarp orders chunk-c reads before chunk-c+2 writes
            }

            float av[4], sv[4] = {s0, s1, s2, s3};
            av[0] = unpack_sum(a20);
            av[1] = unpack_sum(a21);
            av[2] = unpack_sum(a22);
            av[3] = unpack_sum(a23);
#pragma unroll
            for (int ii = 0; ii < TI; ii++) {
                float t = sv[ii];
#pragma unroll
                for (int o = 16; o; o >>= 1) t += __shfl_xor_sync(0xffffffffu, t, o);
                if (lane == 0) sm.a.s[h][seg][ii] = t;
                sm.a.acc[h][seg][ii][lane] = av[ii];
            }
            __syncthreads();

            {
                int ii = warp >> 2, hh = warp & 3;
                float S = sm.a.s[hh][0][ii] + sm.a.s[hh][1][ii]
                        + sm.a.s[hh][2][ii] + sm.a.s[hh][3][ii];
                float A = sm.a.acc[hh][0][ii][lane] + sm.a.acc[hh][1][ii][lane]
                        + sm.a.acc[hh][2][ii][lane] + sm.a.acc[hh][3][ii][lane];
                sm.a.agg[ii][hh * HD + lane] = A / S;
            }
            __syncthreads();

            // ---- LN + relu + residual (warp = row) ----
            if (warp < TI) {
                const int ii = warp;
                float4 x = *(const float4*)&sm.a.agg[ii][lane * 4];
                float m1 = x.x + x.y + x.z + x.w;
                float m2 = x.x*x.x + x.y*x.y + x.z*x.z + x.w*x.w;
#pragma unroll
                for (int o = 16; o; o >>= 1) {
                    m1 += __shfl_xor_sync(0xffffffffu, m1, o);
                    m2 += __shfl_xor_sync(0xffffffffu, m2, o);
                }
                float mu  = m1 * (1.f / HID);
                float var = m2 * (1.f / HID) - mu * mu;
                float rs  = rsqrtf(var + 1e-5f);
                float4 gm = *(const float4*)&gamma[l * HID + lane * 4];
                float4 bt = *(const float4*)&beta[l * HID + lane * 4];
                float4 hv = *(float4*)&g_h[(i0 + ii) * HID + lane * 4];
                hv.x += fmaxf((x.x - mu) * rs * gm.x + bt.x, 0.f);
                hv.y += fmaxf((x.y - mu) * rs * gm.y + bt.y, 0.f);
                hv.z += fmaxf((x.z - mu) * rs * gm.z + bt.z, 0.f);
                hv.w += fmaxf((x.w - mu) * rs * gm.w + bt.w, 0.f);
                if (l < LAYERS - 1) {
                    *(float4*)&g_h[(i0 + ii) * HID + lane * 4] = hv;
                } else {
                    // last layer: final h stays in SMEM for fused heads phase
                    *(float4*)&sm.a.agg[ii][lane * 4] = hv;
                }
            }
        }
        if (l < LAYERS - 1) grid_sync();
    }

    // ================= fused heads phase (final h in sm.a.agg) =================
    {
        __syncthreads();   // all warps see agg rows written by LN warps

        const int i0 = b * TI;
        if (tid < HID)
            g_pool[b * HID + tid] = sm.a.agg[0][tid] + sm.a.agg[1][tid]
                                  + sm.a.agg[2][tid] + sm.a.agg[3][tid];

        int sub = tid & 127, rep = tid >> 7;       // rep = row
        int c = sub & 63, g = sub >> 6;
        const float* W1 = g ? Wd1 : Wn1;
        float a = g ? bd1[c] : bn1[c];
#pragma unroll 4
        for (int k4 = 0; k4 < HID / 4; k4++) {
            float4 hv = *(const float4*)&sm.a.agg[rep][4 * k4];
            a = fmaf(hv.x, W1[(4 * k4 + 0) * 64 + c], a);
            a = fmaf(hv.y, W1[(4 * k4 + 1) * 64 + c], a);
            a = fmaf(hv.z, W1[(4 * k4 + 2) * 64 + c], a);
            a = fmaf(hv.w, W1[(4 * k4 + 3) * 64 + c], a);
        }
        a = fmaxf(a, 0.f);
        float w2a = g ? Wd2[c * 2 + 0] : Wn2[c];
        float w2b = g ? Wd2[c * 2 + 1] : 0.f;
        float ya = a * w2a, yb = a * w2b;
#pragma unroll
        for (int o = 16; o; o >>= 1) {
            ya += __shfl_xor_sync(0xffffffffu, ya, o);
            yb += __shfl_xor_sync(0xffffffffu, yb, o);
        }
        int wq = sub >> 5;  // 0..3 (pair g*2 + half)
        if ((sub & 31) == 0) { redA[rep][wq] = ya; redB[rep][wq] = yb; }
        __syncthreads();

        if (tid < 4) {
            out[i0 + tid] = redA[tid][0] + redA[tid][1] + bn2[0];
        } else if (tid < 8) {
            int r = tid - 4;
            out[NN + 2 * (i0 + r) + 0] = redA[r][2] + redA[r][3] + bd2[0];
            out[NN + 2 * (i0 + r) + 1] = redB[r][2] + redB[r][3] + bd2[1];
        }
    }
    grid_sync();

    // ================= value phase: block 0 =================
    if (b == 0) {
        if (tid < HID) {
            float s = 0.f;
#pragma unroll 8
            for (int bb = 0; bb < GRID; bb++) s += g_pool[bb * HID + tid];
            sm.ps[tid] = s * (1.f / NN);
        }
        __syncthreads();

        float p = 0.f;
        if (tid < 64) {
            float a = bv1[tid];
            for (int k = 0; k < HID; k++) a = fmaf(sm.ps[k], Wv1[k * 64 + tid], a);
            a = fmaxf(a, 0.f);
            p = a * Wv2[tid];
        }
#pragma unroll
        for (int o = 16; o; o >>= 1) p += __shfl_xor_sync(0xffffffffu, p, o);
        __shared__ float red[2];
        if (tid < 64 && (tid & 31) == 0) red[tid >> 5] = p;
        __syncthreads();
        if (tid == 0) out[NN + 2 * NN] = red[0] + red[1] + bv2[0];
    }
}

// ---------------- launch ----------------
extern "C" void kernel_launch(void* const* d_in, const int* in_sizes, int n_in,
                              void* d_out, int out_size) {
    const float* nf    = (const float*)d_in[0];
    const float* adj   = (const float*)d_in[1];
    const float* Wp    = (const float*)d_in[2];
    const float* bp    = (const float*)d_in[3];
    const float* Wl    = (const float*)d_in[4];
    const float* Wr    = (const float*)d_in[5];
    const float* Wv    = (const float*)d_in[6];
    const float* att   = (const float*)d_in[7];
    const float* gamma = (const float*)d_in[8];
    const float* beta  = (const float*)d_in[9];
    const float* Wn1   = (const float*)d_in[10];
    const float* bn1   = (const float*)d_in[11];
    const float* Wn2   = (const float*)d_in[12];
    const float* bn2   = (const float*)d_in[13];
    const float* Wd1   = (const float*)d_in[14];
    const float* bd1   = (const float*)d_in[15];
    const float* Wd2   = (const float*)d_in[16];
    const float* bd2   = (const float*)d_in[17];
    const float* Wv1   = (const float*)d_in[18];
    const float* bv1   = (const float*)d_in[19];
    const float* Wv2   = (const float*)d_in[20];
    const float* bv2   = (const float*)d_in[21];
    float* out = (float*)d_out;

    mega_kernel<<<GRID, TPB>>>(nf, adj, Wp, bp, Wl, Wr, Wv, att, gamma, beta,
                               Wn1, bn1, Wn2, bn2, Wd1, bd1, Wd2, bd2,
                               Wv1, bv1, Wv2, bv2, out);
}

// round 17
// speedup vs baseline: 1.0133x; 1.0133x over previous
#include <cuda_runtime.h>
#include <math_constants.h>

#define NN      1024
#define HID     128
#define HEADS   4
#define HD      32
#define LAYERS  3
#define TI      4          // i-rows per block in attention
#define NSEG    4          // j-segments (warp = head x seg)
#define SEGJ    (NN/NSEG)  // 256
#define ADJW    (NN/32)    // 32 words per adjacency row
#define GRID    256
#define TPB     512

typedef unsigned long long u64;

#define FMA2(acc, x, y) asm("fma.rn.f32x2 %0, %1, %2, %0;" : "+l"(acc) : "l"(x), "l"(y))

__device__ __forceinline__ u64 absadd2(u64 x, u64 y) {
    u64 s;
    asm("add.rn.f32x2 %0, %1, %2;" : "=l"(s) : "l"(x), "l"(y));
    return s & 0x7FFFFFFF7FFFFFFFull;   // packed fabs (LOP3, ALU pipe)
}

__device__ __forceinline__ float unpack_sum(u64 v) {
    float lo, hi;
    asm("mov.b64 {%0, %1}, %2;" : "=f"(lo), "=f"(hi) : "l"(v));
    return lo + hi;
}

__device__ __forceinline__ u64 pack2(float lo, float hi) {
    u64 r;
    asm("mov.b64 %0, {%1, %2};" : "=l"(r) : "f"(lo), "f"(hi));
    return r;
}

__device__ __forceinline__ float ex2f(float x) {
    float r;
    asm("ex2.approx.f32 %0, %1;" : "=f"(r) : "f"(x));
    return r;
}

#define LOG2E 1.4426950408889634f

// ---------------- scratch (no allocs allowed) ----------------
__device__ __align__(128) float    g_h[NN * HID];
__device__ __align__(128) float    g_wlh[NN * HID];
__device__ __align__(128) float    g_wrhT[HID * NN];     // pair-interleaved: [h*16+dp][j][2]
__device__ __align__(128) float    g_v[NN * HID];        // pair-interleaved: [(j>>1)][d][j&1]
__device__ __align__(128) float    g_eb[HEADS * NN];     // log2-domain: 0.6*log2e*sum_d wrh*att
__device__ __align__(128) unsigned g_adjbits[ADJW * NN]; // [word][i] transposed
__device__ __align__(128) float    g_pool[GRID * HID];   // per-block column partials

// ---------------- grid barrier (generation-based, persistent-safe) ----------------
__device__ unsigned          g_cnt = 0;
__device__ volatile unsigned g_gen = 0;
__device__ unsigned          g_done = 0;   // final arrive-only counter

__device__ __forceinline__ void grid_sync() {
    __syncthreads();
    if (threadIdx.x == 0) {
        __threadfence();                       // publish writes + L1 IVALL
        unsigned gen = g_gen;
        if (atomicAdd(&g_cnt, 1) == GRID - 1) {
            g_cnt = 0;
            __threadfence();
            g_gen = gen + 1;
        } else {
            while (g_gen == gen) __nanosleep(32);
        }
        __threadfence();                       // invalidate L1 before new reads
    }
    __syncthreads();
}

// ---------------- shared memory union ----------------
struct AttnSmem {
    float wl[TI][HID];
    float att[HD];
    float p[16][TI][32];                // [warp][ii][jj]
    float s[HEADS][NSEG][TI];
    float acc[HEADS][NSEG][TI][HD];
    float agg[TI][HID];                 // also final-h rows in last layer
};
struct GemmSmem { float hs[16 * 132]; };
union MegaSmem {
    AttnSmem  a;
    GemmSmem  g;
    float     ps[HID];
};

__global__ void __launch_bounds__(TPB, 2)
mega_kernel(const float* __restrict__ nf,   const float* __restrict__ adj,
            const float* __restrict__ Wp,   const float* __restrict__ bp,
            const float* __restrict__ Wl,   const float* __restrict__ Wr,
            const float* __restrict__ Wv,   const float* __restrict__ att,
            const float* __restrict__ gamma,const float* __restrict__ beta,
            const float* __restrict__ Wn1,  const float* __restrict__ bn1,
            const float* __restrict__ Wn2,  const float* __restrict__ bn2,
            const float* __restrict__ Wd1,  const float* __restrict__ bd1,
            const float* __restrict__ Wd2,  const float* __restrict__ bd2,
            const float* __restrict__ Wv1,  const float* __restrict__ bv1,
            const float* __restrict__ Wv2,  const float* __restrict__ bv2,
            float* __restrict__ out) {
    __shared__ MegaSmem sm;
    __shared__ float redA[4][4], redB[4][4];
    const int b    = blockIdx.x;
    const int tid  = threadIdx.x;
    const int warp = tid >> 5;
    const int lane = tid & 31;

    // ================= phase 0: proj + adjbits =================
    {
        int t = b * TPB + tid;            // 0..131071
        int i = t >> 7, c = t & 127;
        float a = bp[c]
                + nf[i * 3 + 0] * Wp[0 * HID + c]
                + nf[i * 3 + 1] * Wp[1 * HID + c]
                + nf[i * 3 + 2] * Wp[2 * HID + c];
        g_h[i * HID + c] = fmaxf(a, 0.f);

        int gw  = b * 16 + warp;          // 0..4095
        int row = gw >> 2, part = gw & 3;
#pragma unroll
        for (int q = 0; q < 8; q++) {
            int w2 = part * 8 + q;
            float v = adj[(size_t)row * NN + w2 * 32 + lane];
            unsigned bits = __ballot_sync(0xffffffffu, v > 0.5f);
            if (lane == 0) g_adjbits[w2 * NN + row] = bits;
        }
    }
    grid_sync();

    // ================= layers =================
    for (int l = 0; l < LAYERS; l++) {
        const float* attL = att + l * HD;

        // ---- gemm3 phase: blocks 0..191, 16 rows/block ----
        if (b < 192) {
            int mode = b >> 6;
            int r0   = (b & 63) * 16;
            const float* W = (mode == 0 ? Wl : (mode == 1 ? Wr : Wv)) + l * HID * HID;
            float* hs = sm.g.hs;
            for (int t = tid; t < 16 * HID; t += TPB)
                hs[(t >> 7) * 132 + (t & 127)] = g_h[r0 * HID + t];
            __syncthreads();

            int c = tid & 127, rg = tid >> 7;   // 4 row-groups x 4 rows
            float acc[4] = {0.f, 0.f, 0.f, 0.f};
#pragma unroll 4
            for (int k4 = 0; k4 < HID / 4; k4++) {
                float w0 = W[(4 * k4 + 0) * HID + c];
                float w1 = W[(4 * k4 + 1) * HID + c];
                float w2 = W[(4 * k4 + 2) * HID + c];
                float w3 = W[(4 * k4 + 3) * HID + c];
#pragma unroll
                for (int r = 0; r < 4; r++) {
                    float4 hv = *(const float4*)&hs[(rg * 4 + r) * 132 + 4 * k4];
                    acc[r] = fmaf(hv.x, w0, acc[r]);
                    acc[r] = fmaf(hv.y, w1, acc[r]);
                    acc[r] = fmaf(hv.z, w2, acc[r]);
                    acc[r] = fmaf(hv.w, w3, acc[r]);
                }
            }

            if (mode == 0) {
#pragma unroll
                for (int r = 0; r < 4; r++)
                    g_wlh[(r0 + rg * 4 + r) * HID + c] = acc[r];
            } else if (mode == 2) {
                // pair-interleaved V: [(row>>1)][d][row&1]
#pragma unroll
                for (int r = 0; r < 4; r++) {
                    int row = r0 + rg * 4 + r;
                    g_v[(row >> 1) * (2 * HID) + c * 2 + (row & 1)] = acc[r];
                }
            } else {
                // eb (log2 domain): warp covers (rg, head = warp&3), c = head*32 + lane
                int head = warp & 3;
                float atv = attL[lane];
#pragma unroll
                for (int r = 0; r < 4; r++) {
                    float bv = acc[r] * atv;
#pragma unroll
                    for (int o = 16; o; o >>= 1) bv += __shfl_xor_sync(0xffffffffu, bv, o);
                    if (lane == 0) g_eb[head * NN + r0 + rg * 4 + r] = 0.6f * LOG2E * bv;
                }
                __syncthreads();
#pragma unroll
                for (int r = 0; r < 4; r++)
                    hs[(rg * 4 + r) * 132 + c] = acc[r];
                __syncthreads();
                // pair-interleaved wrhT: [(cc>>1)][j][cc&1]
                int l16 = tid & 15, grp = tid >> 4;   // 32 groups x 16 lanes
                for (int cc = grp; cc < HID; cc += 32)
                    g_wrhT[((cc >> 1) * NN + r0 + l16) * 2 + (cc & 1)] = hs[l16 * 132 + cc];
            }
        }
        grid_sync();

        // ---- attn phase: all 256 blocks ----
        {
            const int i0  = b * TI;
            const int h   = warp & 3;
            const int seg = warp >> 2;

            for (int t = tid; t < TI * HID; t += TPB)
                sm.a.wl[t >> 7][t & 127] = g_wlh[i0 * HID + t];
            // fold 0.4 * log2(e): hot path uses raw ex2
            if (tid < HD) sm.a.att[tid] = 0.4f * LOG2E * attL[tid];
            __syncthreads();

            float s0 = 0.f, s1 = 0.f, s2 = 0.f, s3 = 0.f;
            u64 a20 = 0, a21 = 0, a22 = 0, a23 = 0;   // packed even/odd-jj agg partials

            const int jbase = seg * SEGJ;
#pragma unroll 1
            for (int c = 0; c < SEGJ / 32; c++) {
                const int j0 = jbase + c * 32;
                const int j  = j0 + lane;

                float leb = g_eb[h * NN + j];              // log2-domain bias
                uint4 aw  = *(const uint4*)&g_adjbits[(j0 >> 5) * NN + i0];

                // init score accumulators with {leb, 0}: the bias rides the FMA2 chain
                u64 linit = pack2(leb, 0.f);
                u64 c20 = linit, c21 = linit, c22 = linit, c23 = linit;
#pragma unroll
                for (int half = 0; half < 2; half++) {
                    u64 wru[8];
#pragma unroll
                    for (int dp = 0; dp < 8; dp++)
                        wru[dp] = *(const u64*)&g_wrhT[((h * 16 + half * 8 + dp) * NN + j) * 2];
#pragma unroll
                    for (int q = 0; q < 4; q++) {
                        ulonglong2 at2 = *(const ulonglong2*)&sm.a.att[half * 16 + 4 * q];
                        u64 wa = wru[2 * q], wb = wru[2 * q + 1];
                        const int off = h * HD + half * 16 + 4 * q;
                        ulonglong2 lw;
                        lw = *(const ulonglong2*)&sm.a.wl[0][off];
                        FMA2(c20, absadd2(lw.x, wa), at2.x);
                        FMA2(c20, absadd2(lw.y, wb), at2.y);
                        lw = *(const ulonglong2*)&sm.a.wl[1][off];
                        FMA2(c21, absadd2(lw.x, wa), at2.x);
                        FMA2(c21, absadd2(lw.y, wb), at2.y);
                        lw = *(const ulonglong2*)&sm.a.wl[2][off];
                        FMA2(c22, absadd2(lw.x, wa), at2.x);
                        FMA2(c22, absadd2(lw.y, wb), at2.y);
                        lw = *(const ulonglong2*)&sm.a.wl[3][off];
                        FMA2(c23, absadd2(lw.x, wa), at2.x);
                        FMA2(c23, absadd2(lw.y, wb), at2.y);
                    }
                }

                float e0 = unpack_sum(c20);
                float e1 = unpack_sum(c21);
                float e2 = unpack_sum(c22);
                float e3 = unpack_sum(c23);
                float p0 = ((aw.x >> lane) & 1u) ? ex2f(e0) : 0.f;
                float p1 = ((aw.y >> lane) & 1u) ? ex2f(e1) : 0.f;
                float p2 = ((aw.z >> lane) & 1u) ? ex2f(e2) : 0.f;
                float p3 = ((aw.w >> lane) & 1u) ? ex2f(e3) : 0.f;
                s0 += p0; s1 += p1; s2 += p2; s3 += p3;

                // transposed store: p[warp][ii][jj=lane]
                sm.a.p[warp][0][lane] = p0;
                sm.a.p[warp][1][lane] = p1;
                sm.a.p[warp][2][lane] = p2;
                sm.a.p[warp][3][lane] = p3;
                __syncwarp();

                // ---- packed aggregation: LDS.128 p-quads + FFMA2 ----
                const float* vp = g_v + (size_t)(j0 >> 1) * (2 * HID) + (h * HD + lane) * 2;
#pragma unroll
                for (int k = 0; k < 8; k++) {
                    u64 vva = *(const u64*)(vp + (2 * k)     * (2 * HID));
                    u64 vvb = *(const u64*)(vp + (2 * k + 1) * (2 * HID));
                    ulonglong2 q0 = *(const ulonglong2*)&sm.a.p[warp][0][4 * k];
                    ulonglong2 q1 = *(const ulonglong2*)&sm.a.p[warp][1][4 * k];
                    ulonglong2 q2 = *(const ulonglong2*)&sm.a.p[warp][2][4 * k];
                    ulonglong2 q3 = *(const ulonglong2*)&sm.a.p[warp][3][4 * k];
                    FMA2(a20, q0.x, vva);
                    FMA2(a21, q1.x, vva);
                    FMA2(a22, q2.x, vva);
                    FMA2(a23, q3.x, vva);
                    FMA2(a20, q0.y, vvb);
                    FMA2(a21, q1.y, vvb);
                    FMA2(a22, q2.y, vvb);
                    FMA2(a23, q3.y, vvb);
                }
                __syncwarp();
            }

            float av[4], sv[4] = {s0, s1, s2, s3};
            av[0] = unpack_sum(a20);
            av[1] = unpack_sum(a21);
            av[2] = unpack_sum(a22);
            av[3] = unpack_sum(a23);
#pragma unroll
            for (int ii = 0; ii < TI; ii++) {
                float t = sv[ii];
#pragma unroll
                for (int o = 16; o; o >>= 1) t += __shfl_xor_sync(0xffffffffu, t, o);
                if (lane == 0) sm.a.s[h][seg][ii] = t;
                sm.a.acc[h][seg][ii][lane] = av[ii];
            }
            __syncthreads();

            {
                int ii = warp >> 2, hh = warp & 3;
                float S = sm.a.s[hh][0][ii] + sm.a.s[hh][1][ii]
                        + sm.a.s[hh][2][ii] + sm.a.s[hh][3][ii];
                float A = sm.a.acc[hh][0][ii][lane] + sm.a.acc[hh][1][ii][lane]
                        + sm.a.acc[hh][2][ii][lane] + sm.a.acc[hh][3][ii][lane];
                sm.a.agg[ii][hh * HD + lane] = A / S;
            }
            __syncthreads();

            // ---- LN + relu + residual (warp = row) ----
            if (warp < TI) {
                const int ii = warp;
                float4 x = *(const float4*)&sm.a.agg[ii][lane * 4];
                float m1 = x.x + x.y + x.z + x.w;
                float m2 = x.x*x.x + x.y*x.y + x.z*x.z + x.w*x.w;
#pragma unroll
                for (int o = 16; o; o >>= 1) {
                    m1 += __shfl_xor_sync(0xffffffffu, m1, o);
                    m2 += __shfl_xor_sync(0xffffffffu, m2, o);
                }
                float mu  = m1 * (1.f / HID);
                float var = m2 * (1.f / HID) - mu * mu;
                float rs  = rsqrtf(var + 1e-5f);
                float4 gm = *(const float4*)&gamma[l * HID + lane * 4];
                float4 bt = *(const float4*)&beta[l * HID + lane * 4];
                float4 hv = *(float4*)&g_h[(i0 + ii) * HID + lane * 4];
                hv.x += fmaxf((x.x - mu) * rs * gm.x + bt.x, 0.f);
                hv.y += fmaxf((x.y - mu) * rs * gm.y + bt.y, 0.f);
                hv.z += fmaxf((x.z - mu) * rs * gm.z + bt.z, 0.f);
                hv.w += fmaxf((x.w - mu) * rs * gm.w + bt.w, 0.f);
                if (l < LAYERS - 1) {
                    *(float4*)&g_h[(i0 + ii) * HID + lane * 4] = hv;
                } else {
                    // last layer: final h stays in SMEM for fused heads phase
                    *(float4*)&sm.a.agg[ii][lane * 4] = hv;
                }
            }
        }
        if (l < LAYERS - 1) grid_sync();
    }

    // ================= fused heads phase (final h in sm.a.agg) =================
    {
        __syncthreads();   // all warps see agg rows written by LN warps

        const int i0 = b * TI;
        if (tid < HID)
            g_pool[b * HID + tid] = sm.a.agg[0][tid] + sm.a.agg[1][tid]
                                  + sm.a.agg[2][tid] + sm.a.agg[3][tid];

        int sub = tid & 127, rep = tid >> 7;       // rep = row
        int c = sub & 63, g = sub >> 6;
        const float* W1 = g ? Wd1 : Wn1;
        float a = g ? bd1[c] : bn1[c];
#pragma unroll 4
        for (int k4 = 0; k4 < HID / 4; k4++) {
            float4 hv = *(const float4*)&sm.a.agg[rep][4 * k4];
            a = fmaf(hv.x, W1[(4 * k4 + 0) * 64 + c], a);
            a = fmaf(hv.y, W1[(4 * k4 + 1) * 64 + c], a);
            a = fmaf(hv.z, W1[(4 * k4 + 2) * 64 + c], a);
            a = fmaf(hv.w, W1[(4 * k4 + 3) * 64 + c], a);
        }
        a = fmaxf(a, 0.f);
        float w2a = g ? Wd2[c * 2 + 0] : Wn2[c];
        float w2b = g ? Wd2[c * 2 + 1] : 0.f;
        float ya = a * w2a, yb = a * w2b;
#pragma unroll
        for (int o = 16; o; o >>= 1) {
            ya += __shfl_xor_sync(0xffffffffu, ya, o);
            yb += __shfl_xor_sync(0xffffffffu, yb, o);
        }
        int wq = sub >> 5;  // 0..3 (pair g*2 + half)
        if ((sub & 31) == 0) { redA[rep][wq] = ya; redB[rep][wq] = yb; }
        __syncthreads();

        if (tid < 4) {
            out[i0 + tid] = redA[tid][0] + redA[tid][1] + bn2[0];
        } else if (tid < 8) {
            int r = tid - 4;
            out[NN + 2 * (i0 + r) + 0] = redA[r][2] + redA[r][3] + bd2[0];
            out[NN + 2 * (i0 + r) + 1] = redB[r][2] + redB[r][3] + bd2[1];
        }
    }

    // ---- arrive-only final barrier: non-zero blocks publish g_pool and exit ----
    __syncthreads();
    if (b != 0) {
        if (tid == 0) {
            __threadfence();
            atomicAdd(&g_done, 1);
        }
        return;
    }
    if (tid == 0) {
        while (atomicAdd(&g_done, 0) < GRID - 1) __nanosleep(32);
        __threadfence();   // invalidate L1 before reading g_pool
    }
    __syncthreads();

    // ================= value phase: block 0 only =================
    {
        if (tid < HID) {
            float s = 0.f;
#pragma unroll 8
            for (int bb = 0; bb < GRID; bb++) s += g_pool[bb * HID + tid];
            sm.ps[tid] = s * (1.f / NN);
        }
        __syncthreads();

        float p = 0.f;
        if (tid < 64) {
            float a = bv1[tid];
            for (int k = 0; k < HID; k++) a = fmaf(sm.ps[k], Wv1[k * 64 + tid], a);
            a = fmaxf(a, 0.f);
            p = a * Wv2[tid];
        }
#pragma unroll
        for (int o = 16; o; o >>= 1) p += __shfl_xor_sync(0xffffffffu, p, o);
        __shared__ float red[2];
        if (tid < 64 && (tid & 31) == 0) red[tid >> 5] = p;
        __syncthreads();
        if (tid == 0) {
            out[NN + 2 * NN] = red[0] + red[1] + bv2[0];
            g_done = 0;   // reset for next graph replay (deterministic state)
        }
    }
}

// ---------------- launch ----------------
extern "C" void kernel_launch(void* const* d_in, const int* in_sizes, int n_in,
                              void* d_out, int out_size) {
    const float* nf    = (const float*)d_in[0];
    const float* adj   = (const float*)d_in[1];
    const float* Wp    = (const float*)d_in[2];
    const float* bp    = (const float*)d_in[3];
    const float* Wl    = (const float*)d_in[4];
    const float* Wr    = (const float*)d_in[5];
    const float* Wv    = (const float*)d_in[6];
    const float* att   = (const float*)d_in[7];
    const float* gamma = (const float*)d_in[8];
    const float* beta  = (const float*)d_in[9];
    const float* Wn1   = (const float*)d_in[10];
    const float* bn1   = (const float*)d_in[11];
    const float* Wn2   = (const float*)d_in[12];
    const float* bn2   = (const float*)d_in[13];
    const float* Wd1   = (const float*)d_in[14];
    const float* bd1   = (const float*)d_in[15];
    const float* Wd2   = (const float*)d_in[16];
    const float* bd2   = (const float*)d_in[17];
    const float* Wv1   = (const float*)d_in[18];
    const float* bv1   = (const float*)d_in[19];
    const float* Wv2   = (const float*)d_in[20];
    const float* bv2   = (const float*)d_in[21];
    float* out = (float*)d_out;

    mega_kernel<<<GRID, TPB>>>(nf, adj, Wp, bp, Wl, Wr, Wv, att, gamma, beta,
                               Wn1, bn1, Wn2, bn2, Wd1, bd1, Wd2, bd2,
                               Wv1, bv1, Wv2, bv2, out);
}